// round 12
// baseline (speedup 1.0000x reference)
#include <cuda_runtime.h>
#include <cstdint>

#define IMG_H 360
#define IMG_W 640
#define N_ROI 128
#define N_CH  196      // GROUP_C(4) * 7 * 7
#define PDY   16       // patch rows (bin-row stripe + halo, <=13 needed)
#define PDX   72       // patch cols (<=69 needed)
#define NPART 8        // row-split per channel inside a CTA
#define NCH2  28       // channels per CTA: 4 groups x 7 pw
#define TPB   (NCH2 * NPART)   // 224 threads
#define SMEM_BYTES (3 * PDY * PDX * 4)   // 13824 B

__device__ float g_bin[N_ROI * N_CH];    // pooled bin values (unique writer per entry)
__device__ int   g_cnt[N_ROI];           // zero-init; reset to 0 by finisher each call

// One conv pixel: cols cL,cM in regs; loads col (x+1) into cR. 3 accum chains.
__device__ __forceinline__ float conv_pixel(const float* __restrict__ patch,
                                            const int ro[9],
                                            float (&cL)[9], float (&cM)[9],
                                            float (&cR)[9],
                                            const float (&w0)[9],
                                            const float (&w1)[9],
                                            const float (&w2)[9],
                                            float bias, int x)
{
    #pragma unroll
    for (int j = 0; j < 9; j++) cR[j] = patch[ro[j] + x + 1];
    float v0 = bias, v1 = 0.0f, v2 = 0.0f;
    #pragma unroll
    for (int j = 0; j < 9; j++) {
        v0 = fmaf(cL[j], w0[j], v0);
        v1 = fmaf(cM[j], w1[j], v1);
        v2 = fmaf(cR[j], w2[j], v2);
    }
    return fmaxf(v0 + (v1 + v2), 0.0f);
}

// One CTA per (roi k, bin-row ph). Last CTA per k reduces bins -> out[k,:].
__global__ __launch_bounds__(TPB)
void psroi_binrow_kernel(const float* __restrict__ mv,     // [2,3,360,640]
                         const float* __restrict__ boxes,  // [128,5]
                         const float* __restrict__ msc,    // [1,2]
                         const float* __restrict__ cw,     // [196,3,3,3]
                         const float* __restrict__ cb,     // [196]
                         float* __restrict__ out)          // [128,4]
{
    extern __shared__ float patch[];            // [3][PDY][PDX]
    __shared__ float spool[NPART * NCH2];
    __shared__ int s_last;

    const int k   = blockIdx.x / 7;
    const int ph  = blockIdx.x - k * 7;
    const int tid = threadIdx.x;
    const int part   = tid / NCH2;              // 0..7
    const int chan28 = tid - part * NCH2;       // 0..27
    const int g  = chan28 & 3;
    const int pw = chan28 >> 2;

    // ---- geometry (uniform) ----
    const float s  = __ldg(&msc[0]);
    const int   bi = (int)__ldg(&boxes[k * 5 + 0]);
    const float x1 = rintf(__ldg(&boxes[k * 5 + 1]) * s);   // jnp.round == rintf
    const float y1 = rintf(__ldg(&boxes[k * 5 + 2]) * s);
    const float x2 = rintf(__ldg(&boxes[k * 5 + 3]) * s);
    const float y2 = rintf(__ldg(&boxes[k * 5 + 4]) * s);

    const float roi_w = fmaxf(x2 - x1, 0.1f);
    const float roi_h = fmaxf(y2 - y1, 0.1f);
    const float bin_h = roi_h / 7.0f;
    const float bin_w = roi_w / 7.0f;

    const float fph = (float)ph;
    const int hs = min(max((int)floorf(fph * bin_h + y1), 0), IMG_H);
    const int he = min(max((int)ceilf((fph + 1.0f) * bin_h + y1), 0), IMG_H);

    const int ws0 = min(max((int)floorf(x1), 0), IMG_W);
    const int we6 = min(max((int)ceilf(7.0f * bin_w + x1), 0), IMG_W);

    const int py0 = hs - 1;                     // patch origin (with halo)
    const int px0 = ws0 - 1;
    const int PHt = min(max(he - hs + 2, 0), PDY);
    const int PWt = min(max(we6 - ws0 + 2, 0), PDX);

    // ---- zero patch (halo / OOB) ----
    {
        float4 z4 = make_float4(0.f, 0.f, 0.f, 0.f);
        float4* p4 = (float4*)patch;
        #pragma unroll
        for (int i = tid; i < 3 * PDY * PDX / 4; i += TPB) p4[i] = z4;
    }
    __syncthreads();

    // ---- cp.async the clipped in-bounds rectangle ----
    {
        const int rlo = max(0, -py0);
        const int rhi = min(PHt, IMG_H - py0);
        const int clo = max(0, -px0);
        const int chi = min(PWt, IMG_W - px0);
        const int nr  = rhi - rlo;
        const int nc  = chi - clo;
        if (nr > 0 && nc > 0) {
            const int plane = nr * nc;
            const int tot   = 3 * plane;
            const float* img = mv + (size_t)bi * 3 * IMG_H * IMG_W;
            for (int i = tid; i < tot; i += TPB) {
                const int ic = i / plane;
                const int j  = i - ic * plane;
                const int r  = rlo + j / nc;
                const int cx = clo + (j - (j / nc) * nc);
                const float* gp = &img[(ic * IMG_H + (py0 + r)) * IMG_W + (px0 + cx)];
                uint32_t sa = (uint32_t)__cvta_generic_to_shared(
                                  &patch[(ic * PDY + r) * PDX + cx]);
                asm volatile("cp.async.ca.shared.global [%0], [%1], 4;\n"
                             :: "r"(sa), "l"(gp));
            }
        }
        asm volatile("cp.async.commit_group;\n" ::: "memory");
        asm volatile("cp.async.wait_group 0;\n" ::: "memory");
    }
    __syncthreads();

    // ---- compute: channel (g, ph, pw), rows split 8 ways ----
    const int c = (g * 7 + ph) * 7 + pw;

    float w0[9], w1[9], w2[9];
    #pragma unroll
    for (int j = 0; j < 9; j++) {
        w0[j] = __ldg(&cw[c * 27 + j * 3 + 0]);
        w1[j] = __ldg(&cw[c * 27 + j * 3 + 1]);
        w2[j] = __ldg(&cw[c * 27 + j * 3 + 2]);
    }
    const float bias = __ldg(&cb[c]);

    const float fpw = (float)pw;
    const int ws = min(max((int)floorf(fpw * bin_w + x1), 0), IMG_W);
    const int we = min(max((int)ceilf((fpw + 1.0f) * bin_w + x1), 0), IMG_W);
    const int area = (he - hs) * (we - ws);

    const int npx = we - ws;
    const int n3  = npx > 0 ? npx / 3 : 0;
    const int rem = npx > 0 ? npx - 3 * n3 : 0;

    float sum = 0.0f;
    for (int yy = hs + part; yy < he; yy += NPART) {
        const int ry = yy - py0;                // 1..PHt-2; window rows safe
        int ro[9];
        #pragma unroll
        for (int ic = 0; ic < 3; ic++)
            #pragma unroll
            for (int ky = 0; ky < 3; ky++)
                ro[ic * 3 + ky] = (ic * PDY + (ry - 1 + ky)) * PDX - px0;

        float a[9], b[9], cc[9];
        #pragma unroll
        for (int j = 0; j < 9; j++) {
            a[j] = patch[ro[j] + ws - 1];
            b[j] = patch[ro[j] + ws];
        }

        int xx = ws;
        for (int t = 0; t < n3; ++t) {
            sum += conv_pixel(patch, ro, a,  b,  cc, w0, w1, w2, bias, xx);
            sum += conv_pixel(patch, ro, b,  cc, a,  w0, w1, w2, bias, xx + 1);
            sum += conv_pixel(patch, ro, cc, a,  b,  w0, w1, w2, bias, xx + 2);
            xx += 3;
        }
        if (rem >= 1)
            sum += conv_pixel(patch, ro, a, b, cc, w0, w1, w2, bias, xx);
        if (rem == 2)
            sum += conv_pixel(patch, ro, b, cc, a, w0, w1, w2, bias, xx + 1);
    }
    spool[part * NCH2 + chan28] = sum;
    __syncthreads();

    // ---- write this CTA's 28 bins (unique writers -> deterministic) ----
    if (tid < NCH2) {
        float sfull = 0.0f;
        #pragma unroll
        for (int p = 0; p < NPART; p++) sfull += spool[p * NCH2 + tid];
        const int gg = tid & 3, pww = tid >> 2;
        const int cc2 = (gg * 7 + ph) * 7 + pww;
        g_bin[k * N_CH + cc2] = (area > 0) ? (sfull / (float)area) : 0.0f;
    }

    // ---- last CTA per k does the 49-bin mean (fixed order => deterministic) ----
    __syncthreads();
    if (tid == 0) {
        __threadfence();                         // publish g_bin writes
        s_last = (atomicAdd(&g_cnt[k], 1) == 6) ? 1 : 0;
    }
    __syncthreads();
    if (s_last) {
        if (tid < 4) {
            const float* bk = &g_bin[k * N_CH + tid * 49];
            float acc = 0.0f;
            #pragma unroll
            for (int j = 0; j < 49; j++) acc += bk[j];
            out[k * 4 + tid] = acc / 49.0f;
        }
        if (tid == 0) g_cnt[k] = 0;              // reset for next graph replay
    }
}

extern "C" void kernel_launch(void* const* d_in, const int* in_sizes, int n_in,
                              void* d_out, int out_size)
{
    const float* mv    = (const float*)d_in[0];  // motion_vectors [2,3,360,640]
    const float* boxes = (const float*)d_in[1];  // boxes_prev [128,5]
    const float* msc   = (const float*)d_in[2];  // motion_vector_scale [1,2]
    const float* cw    = (const float*)d_in[3];  // conv_w [196,3,3,3]
    const float* cb    = (const float*)d_in[4];  // conv_b [196]
    float* out         = (float*)d_out;          // [128,4]

    psroi_binrow_kernel<<<N_ROI * 7, TPB, SMEM_BYTES>>>(mv, boxes, msc, cw, cb, out);
}

// round 13
// speedup vs baseline: 1.1333x; 1.1333x over previous
#include <cuda_runtime.h>
#include <cstdint>

#define IMG_H 360
#define IMG_W 640
#define N_ROI 128
#define N_CH  196      // GROUP_C(4) * 7 * 7
#define PDY   16       // patch rows (bin-row stripe + halo, <=13 needed)
#define PDX   76       // patch cols (<=69 needed; 76 => row stride % 32 = 12, conflict-free)
#define NPART 8        // row-split per channel inside a CTA
#define NCH2  28       // channels per CTA: 4 groups x 7 pw
#define TPB   224      // 7 warps; warp w <-> pw = w (warp-uniform bins)
#define SMEM_BYTES (3 * PDY * PDX * 4)   // 14592 B

__device__ float g_bin[N_ROI * N_CH];    // pooled bin values (unique writer per entry)
__device__ int   g_cnt[N_ROI];           // zero-init; reset by finisher each call

// One conv pixel: cols cL,cM in regs; loads col (x+1) into cR. 3 accum chains.
__device__ __forceinline__ float conv_pixel(const float* __restrict__ patch,
                                            const int ro[9],
                                            float (&cL)[9], float (&cM)[9],
                                            float (&cR)[9],
                                            const float (&w0)[9],
                                            const float (&w1)[9],
                                            const float (&w2)[9],
                                            float bias, int x)
{
    #pragma unroll
    for (int j = 0; j < 9; j++) cR[j] = patch[ro[j] + x + 1];
    float v0 = bias, v1 = 0.0f, v2 = 0.0f;
    #pragma unroll
    for (int j = 0; j < 9; j++) {
        v0 = fmaf(cL[j], w0[j], v0);
        v1 = fmaf(cM[j], w1[j], v1);
        v2 = fmaf(cR[j], w2[j], v2);
    }
    return fmaxf(v0 + (v1 + v2), 0.0f);
}

// One CTA per (roi k, bin-row ph). Warp w handles bin column pw=w.
// Lane = part*4 + g: column loop warp-uniform; 4 g-lanes broadcast LDS.
__global__ __launch_bounds__(TPB)
void psroi_binrow_kernel(const float* __restrict__ mv,     // [2,3,360,640]
                         const float* __restrict__ boxes,  // [128,5]
                         const float* __restrict__ msc,    // [1,2]
                         const float* __restrict__ cw,     // [196,3,3,3]
                         const float* __restrict__ cb,     // [196]
                         float* __restrict__ out)          // [128,4]
{
    extern __shared__ float patch[];            // [3][PDY][PDX]
    __shared__ float spool[TPB];                // [lane][pw] partial sums
    __shared__ int s_last;

    const int k   = blockIdx.x / 7;
    const int ph  = blockIdx.x - k * 7;
    const int tid = threadIdx.x;
    const int pw   = tid >> 5;                  // warp id = bin column (0..6)
    const int lane = tid & 31;
    const int part = lane >> 2;                 // 0..7
    const int g    = lane & 3;                  // 0..3

    // ---- geometry (uniform) ----
    const float s  = __ldg(&msc[0]);
    const int   bi = (int)__ldg(&boxes[k * 5 + 0]);
    const float x1 = rintf(__ldg(&boxes[k * 5 + 1]) * s);   // jnp.round == rintf
    const float y1 = rintf(__ldg(&boxes[k * 5 + 2]) * s);
    const float x2 = rintf(__ldg(&boxes[k * 5 + 3]) * s);
    const float y2 = rintf(__ldg(&boxes[k * 5 + 4]) * s);

    const float roi_w = fmaxf(x2 - x1, 0.1f);
    const float roi_h = fmaxf(y2 - y1, 0.1f);
    const float bin_h = roi_h / 7.0f;
    const float bin_w = roi_w / 7.0f;

    const float fph = (float)ph;
    const int hs = min(max((int)floorf(fph * bin_h + y1), 0), IMG_H);
    const int he = min(max((int)ceilf((fph + 1.0f) * bin_h + y1), 0), IMG_H);

    const int ws0 = min(max((int)floorf(x1), 0), IMG_W);
    const int we6 = min(max((int)ceilf(7.0f * bin_w + x1), 0), IMG_W);

    const int py0 = hs - 1;                     // patch origin (with halo)
    const int px0 = ws0 - 1;
    const int PHt = min(max(he - hs + 2, 0), PDY);
    const int PWt = min(max(we6 - ws0 + 2, 0), PDX);

    // ---- zero patch (halo / OOB) ----
    {
        float4 z4 = make_float4(0.f, 0.f, 0.f, 0.f);
        float4* p4 = (float4*)patch;
        #pragma unroll
        for (int i = tid; i < 3 * PDY * PDX / 4; i += TPB) p4[i] = z4;
    }
    __syncthreads();

    // ---- cp.async the clipped in-bounds rectangle ----
    {
        const int rlo = max(0, -py0);
        const int rhi = min(PHt, IMG_H - py0);
        const int clo = max(0, -px0);
        const int chi = min(PWt, IMG_W - px0);
        const int nr  = rhi - rlo;
        const int nc  = chi - clo;
        if (nr > 0 && nc > 0) {
            const int plane = nr * nc;
            const int tot   = 3 * plane;
            const float* img = mv + (size_t)bi * 3 * IMG_H * IMG_W;
            for (int i = tid; i < tot; i += TPB) {
                const int ic = i / plane;
                const int j  = i - ic * plane;
                const int r  = rlo + j / nc;
                const int cx = clo + (j - (j / nc) * nc);
                const float* gp = &img[(ic * IMG_H + (py0 + r)) * IMG_W + (px0 + cx)];
                uint32_t sa = (uint32_t)__cvta_generic_to_shared(
                                  &patch[(ic * PDY + r) * PDX + cx]);
                asm volatile("cp.async.ca.shared.global [%0], [%1], 4;\n"
                             :: "r"(sa), "l"(gp));
            }
        }
        asm volatile("cp.async.commit_group;\n" ::: "memory");
        asm volatile("cp.async.wait_group 0;\n" ::: "memory");
    }
    __syncthreads();

    // ---- compute: channel (g, ph, pw), rows split 8 ways ----
    const int c = (g * 7 + ph) * 7 + pw;

    float w0[9], w1[9], w2[9];
    #pragma unroll
    for (int j = 0; j < 9; j++) {
        w0[j] = __ldg(&cw[c * 27 + j * 3 + 0]);
        w1[j] = __ldg(&cw[c * 27 + j * 3 + 1]);
        w2[j] = __ldg(&cw[c * 27 + j * 3 + 2]);
    }
    const float bias = __ldg(&cb[c]);

    const float fpw = (float)pw;
    const int ws = min(max((int)floorf(fpw * bin_w + x1), 0), IMG_W);
    const int we = min(max((int)ceilf((fpw + 1.0f) * bin_w + x1), 0), IMG_W);

    const int npx = we - ws;                    // warp-uniform
    const int n3  = npx > 0 ? npx / 3 : 0;
    const int rem = npx > 0 ? npx - 3 * n3 : 0;

    float sum = 0.0f;
    for (int yy = hs + part; yy < he; yy += NPART) {
        const int ry = yy - py0;                // 1..PHt-2; window rows safe
        int ro[9];
        #pragma unroll
        for (int ic = 0; ic < 3; ic++)
            #pragma unroll
            for (int ky = 0; ky < 3; ky++)
                ro[ic * 3 + ky] = (ic * PDY + (ry - 1 + ky)) * PDX - px0;

        float a[9], b[9], cc[9];
        #pragma unroll
        for (int j = 0; j < 9; j++) {
            a[j] = patch[ro[j] + ws - 1];
            b[j] = patch[ro[j] + ws];
        }

        int xx = ws;
        for (int t = 0; t < n3; ++t) {
            sum += conv_pixel(patch, ro, a,  b,  cc, w0, w1, w2, bias, xx);
            sum += conv_pixel(patch, ro, b,  cc, a,  w0, w1, w2, bias, xx + 1);
            sum += conv_pixel(patch, ro, cc, a,  b,  w0, w1, w2, bias, xx + 2);
            xx += 3;
        }
        if (rem >= 1)
            sum += conv_pixel(patch, ro, a, b, cc, w0, w1, w2, bias, xx);
        if (rem == 2)
            sum += conv_pixel(patch, ro, b, cc, a, w0, w1, w2, bias, xx + 1);
    }
    spool[lane * 7 + pw] = sum;                 // [(part*4+g)*7 + pw]
    __syncthreads();

    // ---- write this CTA's 28 bins (unique writers -> deterministic) ----
    if (tid < NCH2) {
        const int g2  = tid / 7;                // 0..3
        const int pw2 = tid - g2 * 7;           // 0..6
        float sfull = 0.0f;
        #pragma unroll
        for (int p = 0; p < NPART; p++)
            sfull += spool[(p * 4 + g2) * 7 + pw2];
        // recompute this bin's area (cheap, uniform inputs)
        const float fpw2 = (float)pw2;
        const int ws2 = min(max((int)floorf(fpw2 * bin_w + x1), 0), IMG_W);
        const int we2 = min(max((int)ceilf((fpw2 + 1.0f) * bin_w + x1), 0), IMG_W);
        const int area2 = (he - hs) * (we2 - ws2);
        const int cc2 = (g2 * 7 + ph) * 7 + pw2;
        g_bin[k * N_CH + cc2] = (area2 > 0) ? (sfull / (float)area2) : 0.0f;
    }

    // ---- last CTA per k does the 49-bin mean (fixed order => deterministic) ----
    __syncthreads();
    if (tid == 0) {
        __threadfence();                         // publish g_bin writes
        s_last = (atomicAdd(&g_cnt[k], 1) == 6) ? 1 : 0;
    }
    __syncthreads();
    if (s_last) {
        if (tid < 4) {
            const float* bk = &g_bin[k * N_CH + tid * 49];
            float acc = 0.0f;
            #pragma unroll
            for (int j = 0; j < 49; j++) acc += bk[j];
            out[k * 4 + tid] = acc / 49.0f;
        }
        if (tid == 0) g_cnt[k] = 0;              // reset for next graph replay
    }
}

extern "C" void kernel_launch(void* const* d_in, const int* in_sizes, int n_in,
                              void* d_out, int out_size)
{
    const float* mv    = (const float*)d_in[0];  // motion_vectors [2,3,360,640]
    const float* boxes = (const float*)d_in[1];  // boxes_prev [128,5]
    const float* msc   = (const float*)d_in[2];  // motion_vector_scale [1,2]
    const float* cw    = (const float*)d_in[3];  // conv_w [196,3,3,3]
    const float* cb    = (const float*)d_in[4];  // conv_b [196]
    float* out         = (float*)d_out;          // [128,4]

    psroi_binrow_kernel<<<N_ROI * 7, TPB, SMEM_BYTES>>>(mv, boxes, msc, cw, cb, out);
}

// round 14
// speedup vs baseline: 1.1486x; 1.0135x over previous
#include <cuda_runtime.h>
#include <cstdint>

#define IMG_H 360
#define IMG_W 640
#define N_ROI 128
#define N_CH  196      // GROUP_C(4) * 7 * 7
#define PDY   16       // patch rows (bin-row stripe + halo, <=13 needed)
#define PDX   76       // patch cols (<=69 needed; stride % 32 = 12, conflict-free)
#define NPART 8        // row-split per channel inside a CTA
#define NCH2  28       // channels per CTA: 4 groups x 7 pw
#define TPB   224      // 7 warps; warp w <-> pw = w (warp-uniform bins)
#define SMEM_BYTES (3 * PDY * PDX * 4)   // 14592 B

__device__ float g_bin[N_ROI * N_CH];    // pooled bin values (unique writer per entry)
__device__ int   g_cnt[N_ROI];           // zero-init; reset by finisher each call

// One conv pixel: cols cL,cM in regs; loads col (x+1) into cR. 3 accum chains.
__device__ __forceinline__ float conv_pixel(const float* __restrict__ patch,
                                            const int ro[9],
                                            float (&cL)[9], float (&cM)[9],
                                            float (&cR)[9],
                                            const float (&w0)[9],
                                            const float (&w1)[9],
                                            const float (&w2)[9],
                                            float bias, int x)
{
    #pragma unroll
    for (int j = 0; j < 9; j++) cR[j] = patch[ro[j] + x + 1];
    float v0 = bias, v1 = 0.0f, v2 = 0.0f;
    #pragma unroll
    for (int j = 0; j < 9; j++) {
        v0 = fmaf(cL[j], w0[j], v0);
        v1 = fmaf(cM[j], w1[j], v1);
        v2 = fmaf(cR[j], w2[j], v2);
    }
    return fmaxf(v0 + (v1 + v2), 0.0f);
}

// One CTA per (roi k, bin-row ph). Warp w handles bin column pw=w.
// Lane = part*4 + g: column loop warp-uniform; 4 g-lanes broadcast LDS.
__global__ __launch_bounds__(TPB)
void psroi_binrow_kernel(const float* __restrict__ mv,     // [2,3,360,640]
                         const float* __restrict__ boxes,  // [128,5]
                         const float* __restrict__ msc,    // [1,2]
                         const float* __restrict__ cw,     // [196,3,3,3]
                         const float* __restrict__ cb,     // [196]
                         float* __restrict__ out)          // [128,4]
{
    extern __shared__ float patch[];            // [3][PDY][PDX]
    __shared__ float spool[TPB];                // [lane][pw] partial sums
    __shared__ int s_last;

    const int k   = blockIdx.x / 7;
    const int ph  = blockIdx.x - k * 7;
    const int tid = threadIdx.x;
    const int pw   = tid >> 5;                  // warp id = bin column (0..6)
    const int lane = tid & 31;
    const int part = lane >> 2;                 // 0..7
    const int g    = lane & 3;                  // 0..3

    // ---- geometry (uniform) ----
    const float s  = __ldg(&msc[0]);
    const int   bi = (int)__ldg(&boxes[k * 5 + 0]);
    const float x1 = rintf(__ldg(&boxes[k * 5 + 1]) * s);   // jnp.round == rintf
    const float y1 = rintf(__ldg(&boxes[k * 5 + 2]) * s);
    const float x2 = rintf(__ldg(&boxes[k * 5 + 3]) * s);
    const float y2 = rintf(__ldg(&boxes[k * 5 + 4]) * s);

    const float roi_w = fmaxf(x2 - x1, 0.1f);
    const float roi_h = fmaxf(y2 - y1, 0.1f);
    const float bin_h = roi_h / 7.0f;
    const float bin_w = roi_w / 7.0f;

    const float fph = (float)ph;
    const int hs = min(max((int)floorf(fph * bin_h + y1), 0), IMG_H);
    const int he = min(max((int)ceilf((fph + 1.0f) * bin_h + y1), 0), IMG_H);

    const int ws0 = min(max((int)floorf(x1), 0), IMG_W);
    const int we6 = min(max((int)ceilf(7.0f * bin_w + x1), 0), IMG_W);

    const int py0 = hs - 1;                     // patch origin (with halo)
    const int px0 = ws0 - 1;
    const int PHt = min(max(he - hs + 2, 0), PDY);
    const int PWt = min(max(we6 - ws0 + 2, 0), PDX);

    // ---- zero patch (halo / OOB) ----
    {
        float4 z4 = make_float4(0.f, 0.f, 0.f, 0.f);
        float4* p4 = (float4*)patch;
        #pragma unroll
        for (int i = tid; i < 3 * PDY * PDX / 4; i += TPB) p4[i] = z4;
    }
    __syncthreads();

    // ---- cp.async the clipped in-bounds rectangle (division-free indexing) ----
    {
        const int rlo = max(0, -py0);
        const int rhi = min(PHt, IMG_H - py0);
        const int clo = max(0, -px0);
        const int chi = min(PWt, IMG_W - px0);
        const int cx0 = lane;                   // 0..31: coalesced columns
        const int rg  = pw;                     // 0..6 : row group
        const float* img = mv + (size_t)bi * 3 * IMG_H * IMG_W;
        #pragma unroll
        for (int ic = 0; ic < 3; ic++) {
            for (int r = rlo + rg; r < rhi; r += 7) {
                const float* grow = &img[(ic * IMG_H + (py0 + r)) * IMG_W + px0];
                uint32_t srow = (uint32_t)__cvta_generic_to_shared(
                                    &patch[(ic * PDY + r) * PDX]);
                for (int cx = clo + cx0; cx < chi; cx += 32) {
                    asm volatile("cp.async.ca.shared.global [%0], [%1], 4;\n"
                                 :: "r"(srow + 4u * (uint32_t)cx),
                                    "l"(grow + cx));
                }
            }
        }
        asm volatile("cp.async.commit_group;\n" ::: "memory");
        asm volatile("cp.async.wait_group 0;\n" ::: "memory");
    }
    __syncthreads();

    // ---- compute: channel (g, ph, pw), rows split 8 ways ----
    const int c = (g * 7 + ph) * 7 + pw;

    float w0[9], w1[9], w2[9];
    #pragma unroll
    for (int j = 0; j < 9; j++) {
        w0[j] = __ldg(&cw[c * 27 + j * 3 + 0]);
        w1[j] = __ldg(&cw[c * 27 + j * 3 + 1]);
        w2[j] = __ldg(&cw[c * 27 + j * 3 + 2]);
    }
    const float bias = __ldg(&cb[c]);

    const float fpw = (float)pw;
    const int ws = min(max((int)floorf(fpw * bin_w + x1), 0), IMG_W);
    const int we = min(max((int)ceilf((fpw + 1.0f) * bin_w + x1), 0), IMG_W);

    const int npx = we - ws;                    // warp-uniform
    const int n3  = npx > 0 ? npx / 3 : 0;
    const int rem = npx > 0 ? npx - 3 * n3 : 0;

    float sum = 0.0f;
    for (int yy = hs + part; yy < he; yy += NPART) {
        const int ry = yy - py0;                // 1..PHt-2; window rows safe
        int ro[9];
        #pragma unroll
        for (int ic = 0; ic < 3; ic++)
            #pragma unroll
            for (int ky = 0; ky < 3; ky++)
                ro[ic * 3 + ky] = (ic * PDY + (ry - 1 + ky)) * PDX - px0;

        float a[9], b[9], cc[9];
        #pragma unroll
        for (int j = 0; j < 9; j++) {
            a[j] = patch[ro[j] + ws - 1];
            b[j] = patch[ro[j] + ws];
        }

        int xx = ws;
        for (int t = 0; t < n3; ++t) {
            sum += conv_pixel(patch, ro, a,  b,  cc, w0, w1, w2, bias, xx);
            sum += conv_pixel(patch, ro, b,  cc, a,  w0, w1, w2, bias, xx + 1);
            sum += conv_pixel(patch, ro, cc, a,  b,  w0, w1, w2, bias, xx + 2);
            xx += 3;
        }
        if (rem >= 1)
            sum += conv_pixel(patch, ro, a, b, cc, w0, w1, w2, bias, xx);
        if (rem == 2)
            sum += conv_pixel(patch, ro, b, cc, a, w0, w1, w2, bias, xx + 1);
    }
    spool[lane * 7 + pw] = sum;                 // [(part*4+g)*7 + pw]
    __syncthreads();

    // ---- write this CTA's 28 bins (unique writers -> deterministic) ----
    if (tid < NCH2) {
        const int g2  = tid / 7;                // 0..3
        const int pw2 = tid - g2 * 7;           // 0..6
        float sfull = 0.0f;
        #pragma unroll
        for (int p = 0; p < NPART; p++)
            sfull += spool[(p * 4 + g2) * 7 + pw2];
        const float fpw2 = (float)pw2;
        const int ws2 = min(max((int)floorf(fpw2 * bin_w + x1), 0), IMG_W);
        const int we2 = min(max((int)ceilf((fpw2 + 1.0f) * bin_w + x1), 0), IMG_W);
        const int area2 = (he - hs) * (we2 - ws2);
        const int cc2 = (g2 * 7 + ph) * 7 + pw2;
        g_bin[k * N_CH + cc2] = (area2 > 0) ? (sfull / (float)area2) : 0.0f;
    }

    // ---- last CTA per k does the 49-bin mean (fixed order => deterministic) ----
    __syncthreads();
    if (tid == 0) {
        __threadfence();                         // publish g_bin writes
        s_last = (atomicAdd(&g_cnt[k], 1) == 6) ? 1 : 0;
    }
    __syncthreads();
    if (s_last) {
        if (tid < 4) {
            const float* bk = &g_bin[k * N_CH + tid * 49];
            float acc = 0.0f;
            #pragma unroll
            for (int j = 0; j < 49; j++) acc += bk[j];
            out[k * 4 + tid] = acc / 49.0f;
        }
        if (tid == 0) g_cnt[k] = 0;              // reset for next graph replay
    }
}

extern "C" void kernel_launch(void* const* d_in, const int* in_sizes, int n_in,
                              void* d_out, int out_size)
{
    const float* mv    = (const float*)d_in[0];  // motion_vectors [2,3,360,640]
    const float* boxes = (const float*)d_in[1];  // boxes_prev [128,5]
    const float* msc   = (const float*)d_in[2];  // motion_vector_scale [1,2]
    const float* cw    = (const float*)d_in[3];  // conv_w [196,3,3,3]
    const float* cb    = (const float*)d_in[4];  // conv_b [196]
    float* out         = (float*)d_out;          // [128,4]

    psroi_binrow_kernel<<<N_ROI * 7, TPB, SMEM_BYTES>>>(mv, boxes, msc, cw, cb, out);
}